// round 2
// baseline (speedup 1.0000x reference)
#include <cuda_runtime.h>
#include <cstdint>

#define BATCH 4
#define CH    64
#define HH    128
#define WW    128
#define NST   16
#define NTOK  (BATCH*HH*WW)

// ---- scratch (static __device__, allocation-free) ----
__device__ float g_dp[NTOK*CH];   // delta, channels-last [tok][c]
__device__ float g_du[NTOK*CH];   // delta*u
__device__ float g_bc[NTOK*32];   // [tok][Bc(16) | Cc(16)]
__device__ float g_yh[NTOK*CH];   // horizontal scan output
__device__ float g_yv[NTOK*CH];   // vertical scan output

__device__ __forceinline__ float ex2f(float x){
    float r; asm("ex2.approx.ftz.f32 %0, %1;" : "=f"(r) : "f"(x)); return r;
}
__device__ __forceinline__ void cp16(void* dst, const void* src){
    unsigned s = (unsigned)__cvta_generic_to_shared(dst);
    asm volatile("cp.async.cg.shared.global [%0], [%1], 16;\n" :: "r"(s), "l"(src));
}

// ============================================================================
// K1: per-token projection + delta. Block = one (b,h) row of 128 tokens.
// ============================================================================
__global__ __launch_bounds__(128) void k_prep(
    const float* __restrict__ x,    // [B][C][H][W]
    const float* __restrict__ xw,   // [36][64]
    const float* __restrict__ dtw,  // [64][4]
    const float* __restrict__ dtb)  // [64]
{
    __shared__ __align__(16) float u_sm[CH*129];   // [c][w] pad 129
    __shared__ __align__(16) float wsmT[CH*36];    // [c][p]
    __shared__ float dtwT[4*CH];                   // [r][d]
    __shared__ float dtb_sm[CH];
    __shared__ float dt_sm[WW*4];                  // [w][r]

    const int tid = threadIdx.x;
    const int bh  = blockIdx.x;
    const int b   = bh >> 7, h = bh & 127;

    // load x tile (coalesced: consecutive tid -> consecutive w)
    for (int i = tid; i < CH*WW; i += 128){
        int c = i >> 7, w = i & 127;
        u_sm[c*129 + w] = x[(((b*CH + c)*HH + h) << 7) + w];
    }
    // weights (transposed into smem)
    for (int i = tid; i < 36*CH; i += 128){
        int p = i >> 6, c = i & 63;
        wsmT[c*36 + p] = xw[i];
    }
    for (int i = tid; i < CH*4; i += 128){
        int d = i >> 2, r = i & 3;
        dtwT[r*CH + d] = dtw[i];
    }
    if (tid < CH) dtb_sm[tid] = dtb[tid];
    __syncthreads();

    // ---- projection: thread = token w, 36 accumulators in regs ----
    {
        const int w = tid;
        float acc[36];
        #pragma unroll
        for (int p = 0; p < 36; ++p) acc[p] = 0.f;
        #pragma unroll 4
        for (int c = 0; c < CH; ++c){
            float u = u_sm[c*129 + w];
            const float4* wr = reinterpret_cast<const float4*>(wsmT + c*36);
            #pragma unroll
            for (int q = 0; q < 9; ++q){
                float4 v = wr[q];
                acc[4*q+0] = fmaf(u, v.x, acc[4*q+0]);
                acc[4*q+1] = fmaf(u, v.y, acc[4*q+1]);
                acc[4*q+2] = fmaf(u, v.z, acc[4*q+2]);
                acc[4*q+3] = fmaf(u, v.w, acc[4*q+3]);
            }
        }
        const long tokbase = (long)bh * WW;
        // Bc/Cc direct write: each thread writes its token's contiguous 128B
        float* bco = g_bc + (tokbase + w)*32;
        #pragma unroll
        for (int j = 0; j < 32; ++j) bco[j] = acc[4+j];
        #pragma unroll
        for (int r = 0; r < 4; ++r) dt_sm[w*4 + r] = acc[r];
    }
    __syncthreads();

    // ---- delta = softplus(dt_raw @ dtw^T + b); du = delta*u ----
    {
        const long tokbase = (long)bh * WW;
        const int d = tid & 63, half = tid >> 6;
        const float w0 = dtwT[d], w1 = dtwT[64+d], w2 = dtwT[128+d], w3 = dtwT[192+d];
        const float bb = dtb_sm[d];
        for (int w = half; w < WW; w += 2){
            float pre = fmaf(dt_sm[w*4+3], w3,
                        fmaf(dt_sm[w*4+2], w2,
                        fmaf(dt_sm[w*4+1], w1,
                        fmaf(dt_sm[w*4+0], w0, bb))));
            float e = __expf(-fabsf(pre));
            float delta = __logf(1.f + e) + fmaxf(pre, 0.f);
            long o = (tokbase + w)*CH + d;          // lanes = consecutive d -> coalesced
            g_dp[o] = delta;
            g_du[o] = delta * u_sm[d*129 + w];
        }
    }
}

// ============================================================================
// K2: selective scan. Block = 1 sequence (64 threads, thread = channel).
// blocks 0..511 horizontal, 512..1023 vertical. cp.async double buffering.
// ============================================================================
__global__ __launch_bounds__(64) void k_scan(const float* __restrict__ A_log)
{
    // 2 buffers x (16 tok x (64 dp + 64 du + 32 bc)) = 2*2560 floats = 20KB
    __shared__ __align__(16) float sm[2*2560];

    const int tid = threadIdx.x;            // channel
    const int S   = blockIdx.x;
    const int vert = (S >= 512);
    const int s    = vert ? S - 512 : S;
    const int b = s >> 7, r = s & 127;

    long tok0; int tstride;
    if (!vert){ tok0 = ((long)b*HH + r)*WW; tstride = 1;  }
    else      { tok0 = (long)b*HH*WW + r;   tstride = WW; }
    float* yout = vert ? g_yv : g_yh;

    // A with log2(e) folded in: dA = exp2(delta * A2[n])
    float A2[NST], hs[NST];
    #pragma unroll
    for (int n = 0; n < NST; ++n){
        A2[n] = -__expf(A_log[tid*NST + n]) * 1.4426950408889634f;
        hs[n] = 0.f;
    }

    auto issue = [&](int t, int bufidx){
        float* dst = sm + bufidx*2560;
        const int tn = t*16;
        for (int k = tid; k < 256; k += 64){
            int l = k >> 4, q = k & 15;
            long tok = tok0 + (long)(tn + l)*tstride;
            cp16(dst +        l*64 + q*4, g_dp + tok*64 + q*4);
            cp16(dst + 1024 + l*64 + q*4, g_du + tok*64 + q*4);
        }
        for (int k = tid; k < 128; k += 64){
            int l = k >> 3, q = k & 7;
            long tok = tok0 + (long)(tn + l)*tstride;
            cp16(dst + 2048 + l*32 + q*4, g_bc + tok*32 + q*4);
        }
    };

    issue(0, 0);
    asm volatile("cp.async.commit_group;\n");

    for (int t = 0; t < 8; ++t){
        if (t < 7) issue(t+1, (t+1)&1);
        asm volatile("cp.async.commit_group;\n");
        asm volatile("cp.async.wait_group 1;\n");
        __syncthreads();

        const float* bp = sm + (t&1)*2560;
        #pragma unroll 2
        for (int l = 0; l < 16; ++l){
            float delta = bp[l*64 + tid];
            float duv   = bp[1024 + l*64 + tid];
            const float4* q4 = reinterpret_cast<const float4*>(bp + 2048 + l*32);
            float4 B0 = q4[0], B1 = q4[1], B2 = q4[2], B3 = q4[3];
            float4 C0 = q4[4], C1 = q4[5], C2 = q4[6], C3 = q4[7];
            float bn[NST] = {B0.x,B0.y,B0.z,B0.w, B1.x,B1.y,B1.z,B1.w,
                             B2.x,B2.y,B2.z,B2.w, B3.x,B3.y,B3.z,B3.w};
            float cn[NST] = {C0.x,C0.y,C0.z,C0.w, C1.x,C1.y,C1.z,C1.w,
                             C2.x,C2.y,C2.z,C2.w, C3.x,C3.y,C3.z,C3.w};
            float ya[4] = {0.f, 0.f, 0.f, 0.f};
            #pragma unroll
            for (int n = 0; n < NST; ++n){
                float dA = ex2f(delta * A2[n]);
                hs[n] = fmaf(dA, hs[n], duv * bn[n]);
                ya[n & 3] = fmaf(hs[n], cn[n], ya[n & 3]);
            }
            float y = (ya[0] + ya[1]) + (ya[2] + ya[3]);
            yout[(tok0 + (long)(t*16 + l)*tstride)*64 + tid] = y;   // coalesced
        }
        __syncthreads();
    }
}

// ============================================================================
// K3: out[b,c,h,w] = y_h + y_v + 2*D[c]*x  (smem transpose for coalescing)
// ============================================================================
__global__ __launch_bounds__(256) void k_comb(
    const float* __restrict__ x, const float* __restrict__ Dp,
    float* __restrict__ out)
{
    __shared__ float sm[CH*33];
    const int tid = threadIdx.x;
    const int blk = blockIdx.x;                 // b*512 + h*4 + wt
    const int wt = blk & 3, h = (blk >> 2) & 127, b = blk >> 9;
    const int w0 = wt * 32;
    const long tokb = ((long)b*HH + h)*WW + w0;

    for (int i = tid; i < 32*CH; i += 256){
        int w = i >> 6, c = i & 63;
        long o = (tokb + w)*CH + c;             // lanes = consecutive c -> coalesced
        sm[c*33 + w] = g_yh[o] + g_yv[o];
    }
    __syncthreads();
    for (int i = tid; i < CH*32; i += 256){
        int c = i >> 5, w = i & 31;
        long a = (((long)b*CH + c)*HH + h)*WW + w0 + w;  // lanes = consecutive w
        out[a] = sm[c*33 + w] + 2.f * Dp[c] * x[a];
    }
}

// ============================================================================
extern "C" void kernel_launch(void* const* d_in, const int* in_sizes, int n_in,
                              void* d_out, int out_size)
{
    const float* x     = (const float*)d_in[0];
    const float* A_log = (const float*)d_in[1];
    const float* D     = (const float*)d_in[2];
    const float* xw    = (const float*)d_in[3];
    const float* dtw   = (const float*)d_in[4];
    const float* dtb   = (const float*)d_in[5];
    float* out = (float*)d_out;

    k_prep<<<BATCH*HH, 128>>>(x, xw, dtw, dtb);
    k_scan<<<1024, 64>>>(A_log);
    k_comb<<<BATCH*HH*(WW/32), 256>>>(x, D, out);
}

// round 3
// speedup vs baseline: 1.0243x; 1.0243x over previous
#include <cuda_runtime.h>
#include <cstdint>

#define BATCH 4
#define CH    64
#define HH    128
#define WW    128
#define NST   16
#define NTOK  (BATCH*HH*WW)

// ---- scratch (static __device__, allocation-free) ----
__device__ float g_dp[NTOK*CH];   // delta, channels-last [tok][c]
__device__ float g_du[NTOK*CH];   // delta*u
__device__ float g_bc[NTOK*32];   // [tok][Bc(16) | Cc(16)]
__device__ float g_yh[NTOK*CH];   // horizontal scan output
__device__ float g_yv[NTOK*CH];   // vertical scan output

__device__ __forceinline__ float ex2f(float x){
    float r; asm("ex2.approx.ftz.f32 %0, %1;" : "=f"(r) : "f"(x)); return r;
}
__device__ __forceinline__ void cp16(void* dst, const void* src){
    unsigned s = (unsigned)__cvta_generic_to_shared(dst);
    asm volatile("cp.async.cg.shared.global [%0], [%1], 16;\n" :: "r"(s), "l"(src));
}

// ============================================================================
// K1: projection + delta. Block = 2 rows (256 tokens), 128 threads,
//     thread t handles token w=t in BOTH rows (2 tokens/thread => weight
//     smem fetches amortized over 2 tokens; u streamed from gmem).
// ============================================================================
__global__ __launch_bounds__(128) void k_prep(
    const float* __restrict__ x,    // [B][C][H][W]
    const float* __restrict__ xw,   // [36][64]
    const float* __restrict__ dtw,  // [64][4]
    const float* __restrict__ dtb)  // [64]
{
    __shared__ __align__(16) float wsmT[CH*36];    // [c][p]  9.2KB
    __shared__ __align__(16) float u_sm[CH*129];   // [c][w] one row, 33KB
    __shared__ float dtwT[4*CH];                   // [r][d]
    __shared__ float dtb_sm[CH];
    __shared__ float dt_sm[2*WW*4];                // [row][w][r]

    const int tid = threadIdx.x;
    const int blk = blockIdx.x;           // 0..255
    const int b   = blk >> 6;             // batch
    const int h0  = (blk & 63) * 2;       // first row of the pair

    // ---- stage weights ----
    for (int i = tid; i < 36*CH; i += 128){
        int p = i >> 6, c = i & 63;
        wsmT[c*36 + p] = xw[i];
    }
    for (int i = tid; i < CH*4; i += 128){
        int d = i >> 2, r = i & 3;
        dtwT[r*CH + d] = dtw[i];
    }
    if (tid < CH) dtb_sm[tid] = dtb[tid];
    __syncthreads();

    // ---- GEMM: 36 outputs x 2 tokens per thread, u direct from gmem ----
    {
        const int w = tid;
        float a0[36], a1[36];
        #pragma unroll
        for (int p = 0; p < 36; ++p){ a0[p] = 0.f; a1[p] = 0.f; }

        const float* xp = x + ((((long)b*CH)*HH + h0) << 7) + w;  // c=0, row h0
        #pragma unroll 2
        for (int c = 0; c < CH; ++c){
            float u0 = xp[(long)c*HH*WW];
            float u1 = xp[(long)c*HH*WW + WW];
            const float4* wr = reinterpret_cast<const float4*>(wsmT + c*36);
            #pragma unroll
            for (int q = 0; q < 9; ++q){
                float4 v = wr[q];
                a0[4*q+0] = fmaf(u0, v.x, a0[4*q+0]);
                a0[4*q+1] = fmaf(u0, v.y, a0[4*q+1]);
                a0[4*q+2] = fmaf(u0, v.z, a0[4*q+2]);
                a0[4*q+3] = fmaf(u0, v.w, a0[4*q+3]);
                a1[4*q+0] = fmaf(u1, v.x, a1[4*q+0]);
                a1[4*q+1] = fmaf(u1, v.y, a1[4*q+1]);
                a1[4*q+2] = fmaf(u1, v.z, a1[4*q+2]);
                a1[4*q+3] = fmaf(u1, v.w, a1[4*q+3]);
            }
        }

        // Bc|Cc: each thread writes two contiguous 128B chunks
        const long tok0 = (((long)b*HH + h0) << 7);
        float4* bco0 = reinterpret_cast<float4*>(g_bc + (tok0 + w)*32);
        float4* bco1 = reinterpret_cast<float4*>(g_bc + (tok0 + WW + w)*32);
        #pragma unroll
        for (int j = 0; j < 8; ++j){
            bco0[j] = make_float4(a0[4+4*j], a0[5+4*j], a0[6+4*j], a0[7+4*j]);
            bco1[j] = make_float4(a1[4+4*j], a1[5+4*j], a1[6+4*j], a1[7+4*j]);
        }
        #pragma unroll
        for (int r = 0; r < 4; ++r){
            dt_sm[w*4 + r]          = a0[r];
            dt_sm[WW*4 + w*4 + r]   = a1[r];
        }
    }

    // ---- phase 2: per row, delta = softplus(...), du = delta*u ----
    const int d = tid & 63, half = tid >> 6;
    const float w0 = dtwT[d], w1 = dtwT[64+d], w2 = dtwT[128+d], w3 = dtwT[192+d];
    const float bb = dtb_sm[d];

    #pragma unroll 1
    for (int r = 0; r < 2; ++r){
        __syncthreads();
        // stage u row (h0+r) into u_sm (coalesced; hot in L1/L2 from GEMM)
        for (int i = tid; i < CH*WW; i += 128){
            int c = i >> 7, w = i & 127;
            u_sm[c*129 + w] = x[(((long)(b*CH + c)*HH + h0 + r) << 7) + w];
        }
        __syncthreads();

        const long tokbase = (((long)b*HH + h0 + r) << 7);
        const float* dts = dt_sm + r*WW*4;
        for (int w = half; w < WW; w += 2){
            float pre = fmaf(dts[w*4+3], w3,
                        fmaf(dts[w*4+2], w2,
                        fmaf(dts[w*4+1], w1,
                        fmaf(dts[w*4+0], w0, bb))));
            float e = __expf(-fabsf(pre));
            float delta = __logf(1.f + e) + fmaxf(pre, 0.f);
            long o = (tokbase + w)*CH + d;       // lanes = consecutive d -> coalesced
            g_dp[o] = delta;
            g_du[o] = delta * u_sm[d*129 + w];
        }
    }
}

// ============================================================================
// K2: selective scan. Block = 1 sequence (64 threads, thread = channel).
// blocks 0..511 horizontal, 512..1023 vertical. cp.async double buffering.
// ============================================================================
__global__ __launch_bounds__(64) void k_scan(const float* __restrict__ A_log)
{
    // 2 buffers x (16 tok x (64 dp + 64 du + 32 bc)) = 2*2560 floats = 20KB
    __shared__ __align__(16) float sm[2*2560];

    const int tid = threadIdx.x;            // channel
    const int S   = blockIdx.x;
    const int vert = (S >= 512);
    const int s    = vert ? S - 512 : S;
    const int b = s >> 7, r = s & 127;

    long tok0; int tstride;
    if (!vert){ tok0 = ((long)b*HH + r)*WW; tstride = 1;  }
    else      { tok0 = (long)b*HH*WW + r;   tstride = WW; }
    float* yout = vert ? g_yv : g_yh;

    // A with log2(e) folded in: dA = exp2(delta * A2[n])
    float A2[NST], hs[NST];
    #pragma unroll
    for (int n = 0; n < NST; ++n){
        A2[n] = -__expf(A_log[tid*NST + n]) * 1.4426950408889634f;
        hs[n] = 0.f;
    }

    auto issue = [&](int t, int bufidx){
        float* dst = sm + bufidx*2560;
        const int tn = t*16;
        for (int k = tid; k < 256; k += 64){
            int l = k >> 4, q = k & 15;
            long tok = tok0 + (long)(tn + l)*tstride;
            cp16(dst +        l*64 + q*4, g_dp + tok*64 + q*4);
            cp16(dst + 1024 + l*64 + q*4, g_du + tok*64 + q*4);
        }
        for (int k = tid; k < 128; k += 64){
            int l = k >> 3, q = k & 7;
            long tok = tok0 + (long)(tn + l)*tstride;
            cp16(dst + 2048 + l*32 + q*4, g_bc + tok*32 + q*4);
        }
    };

    issue(0, 0);
    asm volatile("cp.async.commit_group;\n");

    for (int t = 0; t < 8; ++t){
        if (t < 7) issue(t+1, (t+1)&1);
        asm volatile("cp.async.commit_group;\n");
        asm volatile("cp.async.wait_group 1;\n");
        __syncthreads();

        const float* bp = sm + (t&1)*2560;
        #pragma unroll 2
        for (int l = 0; l < 16; ++l){
            float delta = bp[l*64 + tid];
            float duv   = bp[1024 + l*64 + tid];
            const float4* q4 = reinterpret_cast<const float4*>(bp + 2048 + l*32);
            float4 B0 = q4[0], B1 = q4[1], B2 = q4[2], B3 = q4[3];
            float4 C0 = q4[4], C1 = q4[5], C2 = q4[6], C3 = q4[7];
            float bn[NST] = {B0.x,B0.y,B0.z,B0.w, B1.x,B1.y,B1.z,B1.w,
                             B2.x,B2.y,B2.z,B2.w, B3.x,B3.y,B3.z,B3.w};
            float cn[NST] = {C0.x,C0.y,C0.z,C0.w, C1.x,C1.y,C1.z,C1.w,
                             C2.x,C2.y,C2.z,C2.w, C3.x,C3.y,C3.z,C3.w};
            float ya[4] = {0.f, 0.f, 0.f, 0.f};
            #pragma unroll
            for (int n = 0; n < NST; ++n){
                float dA = ex2f(delta * A2[n]);
                hs[n] = fmaf(dA, hs[n], duv * bn[n]);
                ya[n & 3] = fmaf(hs[n], cn[n], ya[n & 3]);
            }
            float y = (ya[0] + ya[1]) + (ya[2] + ya[3]);
            yout[(tok0 + (long)(t*16 + l)*tstride)*64 + tid] = y;   // coalesced
        }
        __syncthreads();
    }
}

// ============================================================================
// K3: out[b,c,h,w] = y_h + y_v + 2*D[c]*x  (smem transpose for coalescing)
// ============================================================================
__global__ __launch_bounds__(256) void k_comb(
    const float* __restrict__ x, const float* __restrict__ Dp,
    float* __restrict__ out)
{
    __shared__ float sm[CH*33];
    const int tid = threadIdx.x;
    const int blk = blockIdx.x;                 // b*512 + h*4 + wt
    const int wt = blk & 3, h = (blk >> 2) & 127, b = blk >> 9;
    const int w0 = wt * 32;
    const long tokb = ((long)b*HH + h)*WW + w0;

    for (int i = tid; i < 32*CH; i += 256){
        int w = i >> 6, c = i & 63;
        long o = (tokb + w)*CH + c;             // lanes = consecutive c -> coalesced
        sm[c*33 + w] = g_yh[o] + g_yv[o];
    }
    __syncthreads();
    for (int i = tid; i < CH*32; i += 256){
        int c = i >> 5, w = i & 31;
        long a = (((long)b*CH + c)*HH + h)*WW + w0 + w;  // lanes = consecutive w
        out[a] = sm[c*33 + w] + 2.f * Dp[c] * x[a];
    }
}

// ============================================================================
extern "C" void kernel_launch(void* const* d_in, const int* in_sizes, int n_in,
                              void* d_out, int out_size)
{
    const float* x     = (const float*)d_in[0];
    const float* A_log = (const float*)d_in[1];
    const float* D     = (const float*)d_in[2];
    const float* xw    = (const float*)d_in[3];
    const float* dtw   = (const float*)d_in[4];
    const float* dtb   = (const float*)d_in[5];
    float* out = (float*)d_out;

    k_prep<<<BATCH*HH/2, 128>>>(x, xw, dtw, dtb);
    k_scan<<<1024, 64>>>(A_log);
    k_comb<<<BATCH*HH*(WW/32), 256>>>(x, D, out);
}

// round 4
// speedup vs baseline: 1.1213x; 1.0947x over previous
#include <cuda_runtime.h>
#include <cstdint>

#define BATCH 4
#define CH    64
#define HH    128
#define WW    128
#define NST   16
#define NTOK  (BATCH*HH*WW)

// ---- scratch (static __device__, allocation-free) ----
__device__ float g_dp[NTOK*CH];   // delta, channels-last [tok][c]
__device__ float g_du[NTOK*CH];   // delta*u
__device__ float g_bc[NTOK*32];   // [tok][Bc(16) | Cc(16)]
__device__ float g_yh[NTOK*CH];   // horizontal scan output
__device__ float g_yv[NTOK*CH];   // vertical scan output

__device__ __forceinline__ float ex2f(float x){
    float r; asm("ex2.approx.ftz.f32 %0, %1;" : "=f"(r) : "f"(x)); return r;
}
__device__ __forceinline__ void cp16(void* dst, const void* src){
    unsigned s = (unsigned)__cvta_generic_to_shared(dst);
    asm volatile("cp.async.cg.shared.global [%0], [%1], 16;\n" :: "r"(s), "l"(src));
}

// ============================================================================
// K1: projection + delta. Block = 64 tokens (half row), 256 threads.
//     Thread (w, q) computes outputs p in [9q, 9q+9) for token w.
//     Only 9 accumulators/thread -> ~40 regs -> 5 blocks/SM (40 warps).
// ============================================================================
__global__ __launch_bounds__(256) void k_prep(
    const float* __restrict__ x,    // [B][C][H][W]
    const float* __restrict__ xw,   // [36][64]
    const float* __restrict__ dtw,  // [64][4]
    const float* __restrict__ dtb)  // [64]
{
    __shared__ __align__(16) float u_sm[CH][65];     // [c][w]  16.6KB
    __shared__ __align__(16) float wq[4][CH][12];    // [q][c][j] = xw[9q+j][c], 12.3KB
    __shared__ __align__(16) float proj_sm[64][37];  // [w][p]   9.5KB
    __shared__ float dtwT[4*CH];                     // [r][d]
    __shared__ float dtb_sm[CH];

    const int tid = threadIdx.x;
    const int blk = blockIdx.x;            // 0..1023
    const int b    = blk >> 8;
    const int h    = (blk >> 1) & 127;
    const int half = blk & 1;
    const int w0   = half << 6;            // 0 or 64

    // ---- stage u tile (coalesced over w) ----
    for (int i = tid; i < CH*64; i += 256){
        int c = i >> 6, w = i & 63;
        u_sm[c][w] = x[(((long)(b*CH + c)*HH + h) << 7) + w0 + w];
    }
    // ---- stage weights, q-grouped ----
    for (int i = tid; i < 36*CH; i += 256){
        int p = i >> 6, c = i & 63;
        wq[p/9][c][p%9] = xw[i];
    }
    {
        if (tid < CH*4){ int d = tid >> 2, r = tid & 3; dtwT[r*CH + d] = dtw[tid]; }
        if (tid >= 256-CH) dtb_sm[tid-(256-CH)] = dtb[tid-(256-CH)];
    }
    __syncthreads();

    // ---- GEMM: 9 outputs x 1 token per thread ----
    {
        const int w = tid & 63, q = tid >> 6;
        float acc[9];
        #pragma unroll
        for (int j = 0; j < 9; ++j) acc[j] = 0.f;

        #pragma unroll 8
        for (int c = 0; c < CH; ++c){
            float u = u_sm[c][w];
            const float4* wp = reinterpret_cast<const float4*>(&wq[q][c][0]);
            float4 v0 = wp[0], v1 = wp[1];
            float  w8 = wq[q][c][8];
            acc[0] = fmaf(u, v0.x, acc[0]);
            acc[1] = fmaf(u, v0.y, acc[1]);
            acc[2] = fmaf(u, v0.z, acc[2]);
            acc[3] = fmaf(u, v0.w, acc[3]);
            acc[4] = fmaf(u, v1.x, acc[4]);
            acc[5] = fmaf(u, v1.y, acc[5]);
            acc[6] = fmaf(u, v1.z, acc[6]);
            acc[7] = fmaf(u, v1.w, acc[7]);
            acc[8] = fmaf(u, w8,  acc[8]);
        }
        const int pbase = 9*q;
        #pragma unroll
        for (int j = 0; j < 9; ++j) proj_sm[w][pbase + j] = acc[j];
    }
    __syncthreads();

    const long tok0 = (((long)b*HH + h) << 7) + w0;

    // ---- Bc|Cc out, fully coalesced ----
    for (int i = tid; i < 64*32; i += 256){
        int w = i >> 5, j = i & 31;
        g_bc[(tok0 + w)*32 + j] = proj_sm[w][4 + j];
    }

    // ---- delta = softplus(dt_raw @ dtw^T + b); du = delta*u ----
    {
        const int d = tid & 63, wg = tid >> 6;   // wg in 0..3
        const float wA = dtwT[d], wB = dtwT[64+d], wC = dtwT[128+d], wD = dtwT[192+d];
        const float bb = dtb_sm[d];
        #pragma unroll 4
        for (int w = wg; w < 64; w += 4){
            float pre = fmaf(proj_sm[w][3], wD,
                        fmaf(proj_sm[w][2], wC,
                        fmaf(proj_sm[w][1], wB,
                        fmaf(proj_sm[w][0], wA, bb))));
            float e = __expf(-fabsf(pre));
            float delta = __logf(1.f + e) + fmaxf(pre, 0.f);
            long o = (tok0 + w)*CH + d;          // lanes: consecutive d -> coalesced
            g_dp[o] = delta;
            g_du[o] = delta * u_sm[d][w];
        }
    }
}

// ============================================================================
// K2: selective scan. Block = 1 sequence (64 threads, thread = channel).
// blocks 0..511 horizontal, 512..1023 vertical. cp.async double buffering.
// ============================================================================
__global__ __launch_bounds__(64) void k_scan(const float* __restrict__ A_log)
{
    // 2 buffers x (16 tok x (64 dp + 64 du + 32 bc)) = 2*2560 floats = 20KB
    __shared__ __align__(16) float sm[2*2560];

    const int tid = threadIdx.x;            // channel
    const int S   = blockIdx.x;
    const int vert = (S >= 512);
    const int s    = vert ? S - 512 : S;
    const int b = s >> 7, r = s & 127;

    long tok0; int tstride;
    if (!vert){ tok0 = ((long)b*HH + r)*WW; tstride = 1;  }
    else      { tok0 = (long)b*HH*WW + r;   tstride = WW; }
    float* yout = vert ? g_yv : g_yh;

    // A with log2(e) folded in: dA = exp2(delta * A2[n])
    float A2[NST], hs[NST];
    #pragma unroll
    for (int n = 0; n < NST; ++n){
        A2[n] = -__expf(A_log[tid*NST + n]) * 1.4426950408889634f;
        hs[n] = 0.f;
    }

    auto issue = [&](int t, int bufidx){
        float* dst = sm + bufidx*2560;
        const int tn = t*16;
        for (int k = tid; k < 256; k += 64){
            int l = k >> 4, q = k & 15;
            long tok = tok0 + (long)(tn + l)*tstride;
            cp16(dst +        l*64 + q*4, g_dp + tok*64 + q*4);
            cp16(dst + 1024 + l*64 + q*4, g_du + tok*64 + q*4);
        }
        for (int k = tid; k < 128; k += 64){
            int l = k >> 3, q = k & 7;
            long tok = tok0 + (long)(tn + l)*tstride;
            cp16(dst + 2048 + l*32 + q*4, g_bc + tok*32 + q*4);
        }
    };

    issue(0, 0);
    asm volatile("cp.async.commit_group;\n");

    for (int t = 0; t < 8; ++t){
        if (t < 7) issue(t+1, (t+1)&1);
        asm volatile("cp.async.commit_group;\n");
        asm volatile("cp.async.wait_group 1;\n");
        __syncthreads();

        const float* bp = sm + (t&1)*2560;
        #pragma unroll 2
        for (int l = 0; l < 16; ++l){
            float delta = bp[l*64 + tid];
            float duv   = bp[1024 + l*64 + tid];
            const float4* q4 = reinterpret_cast<const float4*>(bp + 2048 + l*32);
            float4 B0 = q4[0], B1 = q4[1], B2 = q4[2], B3 = q4[3];
            float4 C0 = q4[4], C1 = q4[5], C2 = q4[6], C3 = q4[7];
            float bn[NST] = {B0.x,B0.y,B0.z,B0.w, B1.x,B1.y,B1.z,B1.w,
                             B2.x,B2.y,B2.z,B2.w, B3.x,B3.y,B3.z,B3.w};
            float cn[NST] = {C0.x,C0.y,C0.z,C0.w, C1.x,C1.y,C1.z,C1.w,
                             C2.x,C2.y,C2.z,C2.w, C3.x,C3.y,C3.z,C3.w};
            float ya[4] = {0.f, 0.f, 0.f, 0.f};
            #pragma unroll
            for (int n = 0; n < NST; ++n){
                float dA = ex2f(delta * A2[n]);
                hs[n] = fmaf(dA, hs[n], duv * bn[n]);
                ya[n & 3] = fmaf(hs[n], cn[n], ya[n & 3]);
            }
            float y = (ya[0] + ya[1]) + (ya[2] + ya[3]);
            yout[(tok0 + (long)(t*16 + l)*tstride)*64 + tid] = y;   // coalesced
        }
        __syncthreads();
    }
}

// ============================================================================
// K3: out[b,c,h,w] = y_h + y_v + 2*D[c]*x  (smem transpose for coalescing)
// ============================================================================
__global__ __launch_bounds__(256) void k_comb(
    const float* __restrict__ x, const float* __restrict__ Dp,
    float* __restrict__ out)
{
    __shared__ float sm[CH*33];
    const int tid = threadIdx.x;
    const int blk = blockIdx.x;                 // b*512 + h*4 + wt
    const int wt = blk & 3, h = (blk >> 2) & 127, b = blk >> 9;
    const int w0 = wt * 32;
    const long tokb = ((long)b*HH + h)*WW + w0;

    for (int i = tid; i < 32*CH; i += 256){
        int w = i >> 6, c = i & 63;
        long o = (tokb + w)*CH + c;             // lanes = consecutive c -> coalesced
        sm[c*33 + w] = g_yh[o] + g_yv[o];
    }
    __syncthreads();
    for (int i = tid; i < CH*32; i += 256){
        int c = i >> 5, w = i & 31;
        long a = (((long)b*CH + c)*HH + h)*WW + w0 + w;  // lanes = consecutive w
        out[a] = sm[c*33 + w] + 2.f * Dp[c] * x[a];
    }
}

// ============================================================================
extern "C" void kernel_launch(void* const* d_in, const int* in_sizes, int n_in,
                              void* d_out, int out_size)
{
    const float* x     = (const float*)d_in[0];
    const float* A_log = (const float*)d_in[1];
    const float* D     = (const float*)d_in[2];
    const float* xw    = (const float*)d_in[3];
    const float* dtw   = (const float*)d_in[4];
    const float* dtb   = (const float*)d_in[5];
    float* out = (float*)d_out;

    k_prep<<<BATCH*HH*2, 256>>>(x, xw, dtw, dtb);
    k_scan<<<1024, 64>>>(A_log);
    k_comb<<<BATCH*HH*(WW/32), 256>>>(x, D, out);
}

// round 5
// speedup vs baseline: 1.1476x; 1.0235x over previous
#include <cuda_runtime.h>
#include <cstdint>

#define BATCH 4
#define CH    64
#define HH    128
#define WW    128
#define NST   16
#define NTOK  (BATCH*HH*WW)

// ---- scratch (static __device__, allocation-free) ----
__device__ float g_dp[NTOK*CH];   // delta, channels-last [tok][c]
__device__ float g_du[NTOK*CH];   // delta*u
__device__ float g_bc[NTOK*32];   // [tok][Bc(16) | Cc(16)]
__device__ float g_yh[NTOK*CH];   // horizontal scan output
__device__ float g_yv[NTOK*CH];   // vertical scan output

__device__ __forceinline__ float ex2f(float x){
    float r; asm("ex2.approx.ftz.f32 %0, %1;" : "=f"(r) : "f"(x)); return r;
}
__device__ __forceinline__ void cp16(void* dst, const void* src){
    unsigned s = (unsigned)__cvta_generic_to_shared(dst);
    asm volatile("cp.async.cg.shared.global [%0], [%1], 16;\n" :: "r"(s), "l"(src));
}
// ---- packed f32x2 helpers (Blackwell FFMA2 path) ----
__device__ __forceinline__ unsigned long long pk2(float lo, float hi){
    unsigned long long r; asm("mov.b64 %0, {%1,%2};" : "=l"(r) : "f"(lo), "f"(hi)); return r;
}
__device__ __forceinline__ void upk2(float& lo, float& hi, unsigned long long v){
    asm("mov.b64 {%0,%1}, %2;" : "=f"(lo), "=f"(hi) : "l"(v));
}
__device__ __forceinline__ unsigned long long mul2(unsigned long long a, unsigned long long b){
    unsigned long long r; asm("mul.rn.f32x2 %0, %1, %2;" : "=l"(r) : "l"(a), "l"(b)); return r;
}
__device__ __forceinline__ unsigned long long fmap2(unsigned long long a, unsigned long long b, unsigned long long c){
    unsigned long long r; asm("fma.rn.f32x2 %0, %1, %2, %3;" : "=l"(r) : "l"(a), "l"(b), "l"(c)); return r;
}
__device__ __forceinline__ unsigned long long addp2(unsigned long long a, unsigned long long b){
    unsigned long long r; asm("add.rn.f32x2 %0, %1, %2;" : "=l"(r) : "l"(a), "l"(b)); return r;
}

// ============================================================================
// K1: projection + delta. Block = 1 row (128 tokens), 256 threads.
//     GEMM: thread (w2 = tid&63, q = tid>>6) computes 9 outputs (p in
//     [9q,9q+9)) for 2 tokens {2w2, 2w2+1}. 18 accumulators, u from gmem.
// ============================================================================
__global__ __launch_bounds__(256) void k_prep(
    const float* __restrict__ x,    // [B][C][H][W]
    const float* __restrict__ xw,   // [36][64]
    const float* __restrict__ dtw,  // [64][4]
    const float* __restrict__ dtb)  // [64]
{
    __shared__ __align__(16) float wq[4][CH][12];    // [q][c][j] = xw[9q+j][c] 12.3KB
    __shared__ __align__(16) float proj_sm[128][37]; // [w][p] 18.9KB
    __shared__ float dtwT[4*CH];                     // [r][d]
    __shared__ float dtb_sm[CH];

    const int tid = threadIdx.x;
    const int blk = blockIdx.x;            // 0..511
    const int b   = blk >> 7;
    const int h   = blk & 127;

    // ---- stage weights ----
    for (int i = tid; i < 36*CH; i += 256){
        int p = i >> 6, c = i & 63;
        wq[p/9][c][p%9] = xw[i];
    }
    if (tid < CH*4){ int d = tid >> 2, r = tid & 3; dtwT[r*CH + d] = dtw[tid]; }
    if (tid < CH)   dtb_sm[tid] = dtb[tid];
    __syncthreads();

    const long rowbase = ((long)b*CH*HH + h) * WW;   // x offset at c=0

    // ---- GEMM ----
    {
        const int w2 = tid & 63, q = tid >> 6;
        float a0[9], a1[9];
        #pragma unroll
        for (int j = 0; j < 9; ++j){ a0[j] = 0.f; a1[j] = 0.f; }

        const float* xp = x + rowbase + 2*w2;
        #pragma unroll 4
        for (int c = 0; c < CH; ++c){
            float2 u = *reinterpret_cast<const float2*>(xp + (long)c*HH*WW);
            const float4* wp = reinterpret_cast<const float4*>(&wq[q][c][0]);
            float4 v0 = wp[0], v1 = wp[1];
            float  w8 = wq[q][c][8];
            a0[0] = fmaf(u.x, v0.x, a0[0]);  a1[0] = fmaf(u.y, v0.x, a1[0]);
            a0[1] = fmaf(u.x, v0.y, a0[1]);  a1[1] = fmaf(u.y, v0.y, a1[1]);
            a0[2] = fmaf(u.x, v0.z, a0[2]);  a1[2] = fmaf(u.y, v0.z, a1[2]);
            a0[3] = fmaf(u.x, v0.w, a0[3]);  a1[3] = fmaf(u.y, v0.w, a1[3]);
            a0[4] = fmaf(u.x, v1.x, a0[4]);  a1[4] = fmaf(u.y, v1.x, a1[4]);
            a0[5] = fmaf(u.x, v1.y, a0[5]);  a1[5] = fmaf(u.y, v1.y, a1[5]);
            a0[6] = fmaf(u.x, v1.z, a0[6]);  a1[6] = fmaf(u.y, v1.z, a1[6]);
            a0[7] = fmaf(u.x, v1.w, a0[7]);  a1[7] = fmaf(u.y, v1.w, a1[7]);
            a0[8] = fmaf(u.x, w8,   a0[8]);  a1[8] = fmaf(u.y, w8,   a1[8]);
        }
        const int pb = 9*q;
        #pragma unroll
        for (int j = 0; j < 9; ++j){
            proj_sm[2*w2  ][pb + j] = a0[j];
            proj_sm[2*w2+1][pb + j] = a1[j];
        }
    }
    __syncthreads();

    const long tok0 = ((long)b*HH + h) << 7;

    // ---- Bc|Cc out, fully coalesced ----
    for (int i = tid; i < 128*32; i += 256){
        int w = i >> 5, j = i & 31;
        g_bc[(tok0 + w)*32 + j] = proj_sm[w][4 + j];
    }

    // ---- delta = softplus(dt_raw @ dtw^T + b); du = delta*u ----
    // thread = (w = tid&127, chalf = tid>>7): 32 channels per thread,
    // contiguous float4 stores into [tok][c] layout.
    {
        const int w   = tid & 127;
        const int c0  = (tid >> 7) * 32;
        const float dt0 = proj_sm[w][0], dt1 = proj_sm[w][1];
        const float dt2 = proj_sm[w][2], dt3 = proj_sm[w][3];
        const float* xr = x + rowbase + w;       // + c*HH*WW per channel
        float* dpw = g_dp + (tok0 + w)*CH;
        float* duw = g_du + (tok0 + w)*CH;

        #pragma unroll 2
        for (int cb = c0; cb < c0 + 32; cb += 4){
            float4 dp4, du4;
            #pragma unroll
            for (int cc = 0; cc < 4; ++cc){
                int c = cb + cc;
                float pre = fmaf(dt3, dtwT[192+c],
                            fmaf(dt2, dtwT[128+c],
                            fmaf(dt1, dtwT[ 64+c],
                            fmaf(dt0, dtwT[c], dtb_sm[c]))));
                float e = __expf(-fabsf(pre));
                float delta = __logf(1.f + e) + fmaxf(pre, 0.f);
                float u = xr[(long)c*HH*WW];     // lane=w -> coalesced
                (&dp4.x)[cc] = delta;
                (&du4.x)[cc] = delta * u;
            }
            *reinterpret_cast<float4*>(dpw + cb) = dp4;
            *reinterpret_cast<float4*>(duw + cb) = du4;
        }
    }
}

// ============================================================================
// K2: selective scan, packed f32x2 math. Block = 1 sequence (64 threads,
// thread = channel). blocks 0..511 horizontal, 512..1023 vertical.
// ============================================================================
__global__ __launch_bounds__(64) void k_scan(const float* __restrict__ A_log)
{
    // 2 buffers x (16 tok x (64 dp + 64 du + 32 bc)) = 2*2560 floats = 20KB
    __shared__ __align__(16) float sm[2*2560];

    const int tid = threadIdx.x;            // channel
    const int S   = blockIdx.x;
    const int vert = (S >= 512);
    const int s    = vert ? S - 512 : S;
    const int b = s >> 7, r = s & 127;

    long tok0; int tstride;
    if (!vert){ tok0 = ((long)b*HH + r)*WW; tstride = 1;  }
    else      { tok0 = (long)b*HH*WW + r;   tstride = WW; }
    float* yout = vert ? g_yv : g_yh;

    // A with log2(e) folded in, packed in pairs: dA = exp2(delta * A2[n])
    unsigned long long A2p[8], hsp[8];
    #pragma unroll
    for (int j = 0; j < 8; ++j){
        float alo = -__expf(A_log[tid*NST + 2*j    ]) * 1.4426950408889634f;
        float ahi = -__expf(A_log[tid*NST + 2*j + 1]) * 1.4426950408889634f;
        A2p[j] = pk2(alo, ahi);
        hsp[j] = 0ull;                      // two packed 0.0f
    }

    auto issue = [&](int t, int bufidx){
        float* dst = sm + bufidx*2560;
        const int tn = t*16;
        for (int k = tid; k < 256; k += 64){
            int l = k >> 4, q = k & 15;
            long tok = tok0 + (long)(tn + l)*tstride;
            cp16(dst +        l*64 + q*4, g_dp + tok*64 + q*4);
            cp16(dst + 1024 + l*64 + q*4, g_du + tok*64 + q*4);
        }
        for (int k = tid; k < 128; k += 64){
            int l = k >> 3, q = k & 7;
            long tok = tok0 + (long)(tn + l)*tstride;
            cp16(dst + 2048 + l*32 + q*4, g_bc + tok*32 + q*4);
        }
    };

    issue(0, 0);
    asm volatile("cp.async.commit_group;\n");

    for (int t = 0; t < 8; ++t){
        if (t < 7) issue(t+1, (t+1)&1);
        asm volatile("cp.async.commit_group;\n");
        asm volatile("cp.async.wait_group 1;\n");
        __syncthreads();

        const float* bp = sm + (t&1)*2560;
        #pragma unroll 2
        for (int l = 0; l < 16; ++l){
            float delta = bp[l*64 + tid];
            float duv   = bp[1024 + l*64 + tid];
            unsigned long long d2  = pk2(delta, delta);
            unsigned long long uv2 = pk2(duv, duv);

            const ulonglong2* q16 = reinterpret_cast<const ulonglong2*>(bp + 2048 + l*32);
            ulonglong2 B01 = q16[0], B23 = q16[1], B45 = q16[2], B67 = q16[3];
            ulonglong2 C01 = q16[4], C23 = q16[5], C45 = q16[6], C67 = q16[7];
            unsigned long long bn2[8] = {B01.x,B01.y,B23.x,B23.y,B45.x,B45.y,B67.x,B67.y};
            unsigned long long cn2[8] = {C01.x,C01.y,C23.x,C23.y,C45.x,C45.y,C67.x,C67.y};

            unsigned long long ya0=0ull, ya1=0ull, ya2=0ull, ya3=0ull;
            #pragma unroll
            for (int j = 0; j < 8; ++j){
                unsigned long long xa = mul2(d2, A2p[j]);
                float lo, hi; upk2(lo, hi, xa);
                unsigned long long dA2 = pk2(ex2f(lo), ex2f(hi));
                unsigned long long db  = mul2(uv2, bn2[j]);
                hsp[j] = fmap2(dA2, hsp[j], db);
                unsigned long long* ya = (j&2) ? ((j&1)? &ya3 : &ya2)
                                               : ((j&1)? &ya1 : &ya0);
                *ya = fmap2(hsp[j], cn2[j], *ya);
            }
            unsigned long long sA = addp2(ya0, ya1);
            unsigned long long sB = addp2(ya2, ya3);
            unsigned long long sT = addp2(sA, sB);
            float slo, shi; upk2(slo, shi, sT);
            yout[(tok0 + (long)(t*16 + l)*tstride)*64 + tid] = slo + shi;  // coalesced
        }
        __syncthreads();
    }
}

// ============================================================================
// K3: out[b,c,h,w] = y_h + y_v + 2*D[c]*x  (smem transpose for coalescing)
// ============================================================================
__global__ __launch_bounds__(256) void k_comb(
    const float* __restrict__ x, const float* __restrict__ Dp,
    float* __restrict__ out)
{
    __shared__ float sm[CH*33];
    const int tid = threadIdx.x;
    const int blk = blockIdx.x;                 // b*512 + h*4 + wt
    const int wt = blk & 3, h = (blk >> 2) & 127, b = blk >> 9;
    const int w0 = wt * 32;
    const long tokb = ((long)b*HH + h)*WW + w0;

    for (int i = tid; i < 32*CH; i += 256){
        int w = i >> 6, c = i & 63;
        long o = (tokb + w)*CH + c;             // lanes = consecutive c -> coalesced
        sm[c*33 + w] = g_yh[o] + g_yv[o];
    }
    __syncthreads();
    for (int i = tid; i < CH*32; i += 256){
        int c = i >> 5, w = i & 31;
        long a = (((long)b*CH + c)*HH + h)*WW + w0 + w;  // lanes = consecutive w
        out[a] = sm[c*33 + w] + 2.f * Dp[c] * x[a];
    }
}

// ============================================================================
extern "C" void kernel_launch(void* const* d_in, const int* in_sizes, int n_in,
                              void* d_out, int out_size)
{
    const float* x     = (const float*)d_in[0];
    const float* A_log = (const float*)d_in[1];
    const float* D     = (const float*)d_in[2];
    const float* xw    = (const float*)d_in[3];
    const float* dtw   = (const float*)d_in[4];
    const float* dtb   = (const float*)d_in[5];
    float* out = (float*)d_out;

    k_prep<<<BATCH*HH, 256>>>(x, xw, dtw, dtb);
    k_scan<<<1024, 64>>>(A_log);
    k_comb<<<BATCH*HH*(WW/32), 256>>>(x, D, out);
}